// round 15
// baseline (speedup 1.0000x reference)
#include <cuda_runtime.h>
#include <cuda_fp16.h>
#include <math_constants.h>
#include <cstdint>

// VectorQuantizer: 1-pass fp16 mma.sync filter -> fp16 S-matrix in smem ->
// one-time scan (min + band) -> exact fp32 rescore of band cols.
// latents [65536,64] f32, embedding [512,64] f32.
// out[0] = vq_loss, out[1..] = quantized_st (4B-aligned -> scalar stores).
//
// h = b - S/256, S = sum hi16(x)*hi16(512e). Filter error <= ~3.4e-4,
// fp16 storage of S adds <= ~2.4e-4 -> exact winner lies within 1.2e-3 of the
// stored min; BAND = 3e-3 (2.5x margin). Scan covers ALL 512 cols (no top-k
// loss, no fallback): unconditionally sound. Band cols rescored with the
// R13-validated exact chain (fmaf ascending, fl(fl(a+b)-2c), first-index ties
// via packed-key atomicMin).
// R15 lesson: per-nt candidate maintenance (R13 atomics / R14 select chains)
// costs more than the saved MMAs; per-nt work here = 2 cvt + 2 STS, stateless.

#define NROWS 65536
#define KEMB 512
#define DDIM 64
#define TILE_M 64
#define NCTAS (NROWS / TILE_M)   // 1024
#define NTHREADS 128             // 4 warps; warp owns 16 rows (1 m16 tile)
#define NT_TILES (KEMB / 8)      // 64
#define KT 4                     // K = 64 = 4 x k16
#define BAND 3e-3f
#define HSTRIDE 524              // halfs per row: 1048 B (2-way-max LDS.64 banks)
#define INV256 0.00390625f

__device__ uint2  g_epack[KT * KEMB * 4];  // 64 KB: B cells (hi only)
__device__ float  g_bn[KEMB];              // ||e||^2 exact chains
__device__ double g_part[NCTAS];
__device__ int    g_cnt = 0;               // last-CTA ticket (self-resetting)

__device__ __forceinline__ uint32_t pack_h2(__half lo, __half hi) {
    return (uint32_t)__half_as_ushort(lo) | ((uint32_t)__half_as_ushort(hi) << 16);
}
__device__ __forceinline__ void mma_f16(float* d, const uint4 a,
                                        uint32_t b0, uint32_t b1) {
    asm volatile(
        "mma.sync.aligned.m16n8k16.row.col.f32.f16.f16.f32 "
        "{%0,%1,%2,%3}, {%4,%5,%6,%7}, {%8,%9}, {%0,%1,%2,%3};"
        : "+f"(d[0]), "+f"(d[1]), "+f"(d[2]), "+f"(d[3])
        : "r"(a.x), "r"(a.y), "r"(a.z), "r"(a.w), "r"(b0), "r"(b1));
}
// exact R1-class distance: ascending-d fmaf chain + fl(fl(a+b) - 2c)
__device__ __forceinline__ float exact_dist4(const float* __restrict__ x,
                                             const float* __restrict__ e,
                                             float a, float b) {
    float c = 0.f;
    #pragma unroll
    for (int d = 0; d < DDIM; d += 4) {
        float4 xv = __ldg((const float4*)(x + d));
        float4 ev = __ldg((const float4*)(e + d));
        c = __fmaf_rn(xv.x, ev.x, c);
        c = __fmaf_rn(xv.y, ev.y, c);
        c = __fmaf_rn(xv.z, ev.z, c);
        c = __fmaf_rn(xv.w, ev.w, c);
    }
    return __fsub_rn(__fadd_rn(a, b), 2.0f * c);
}

// ---------------- pre-kernel (8 blocks): E hi-cells + ||e||^2 ----------------
__global__ __launch_bounds__(128)
void vq_epack_kernel(const float* __restrict__ emb) {
    const int tid = threadIdx.x;
    const int b = blockIdx.x;
    if (tid < 64) {                 // Bn: sequential fp32 chain on raw e
        int n = b * 64 + tid;
        const float* e = emb + (size_t)n * DDIM;
        float s = 0.f;
        #pragma unroll
        for (int d = 0; d < DDIM; d++)
            s = __fadd_rn(s, __fmul_rn(e[d], e[d]));
        g_bn[n] = s;
    }
    #pragma unroll
    for (int s = 0; s < 8; s++) {
        int ci = s * 128 + tid;
        int kt = ci >> 8, rem = ci & 255;
        int nl = rem >> 2, qs = rem & 3;
        int n = b * 64 + nl;
        int k0 = kt * 16 + 2 * qs;
        float2 e01 = __ldg((const float2*)(emb + (size_t)n * DDIM + k0));
        float2 e89 = __ldg((const float2*)(emb + (size_t)n * DDIM + k0 + 8));
        __half h0 = __float2half_rn(512.f * e01.x);
        __half h1 = __float2half_rn(512.f * e01.y);
        __half h2 = __float2half_rn(512.f * e89.x);
        __half h3 = __float2half_rn(512.f * e89.y);
        g_epack[(kt * KEMB + n) * 4 + qs] = make_uint2(pack_h2(h0, h1), pack_h2(h2, h3));
    }
}

// ---------------- main kernel ----------------
__global__ __launch_bounds__(NTHREADS)
void vq_mma_kernel(const float* __restrict__ lat,
                   const float* __restrict__ emb,
                   float* __restrict__ out /* d_out; quant = out+1 */)
{
    extern __shared__ __half hS[];   // [TILE_M][HSTRIDE] fp16 S values (67,072 B)
    __shared__ float    BnS[KEMB];
    __shared__ float    AsS[TILE_M];
    __shared__ unsigned long long mkey[TILE_M];
    __shared__ int      IdxS[TILE_M];
    __shared__ double   Wsum[4];
    __shared__ int      lastFlag;

    float* quant = out + 1;

    const int tid  = threadIdx.x;
    const int w    = tid >> 5;
    const int lane = tid & 31;
    const int qid  = lane >> 2;
    const int qsub = lane & 3;
    const int rowBase = blockIdx.x * TILE_M;

    #pragma unroll
    for (int i = 0; i < 4; i++) BnS[i * NTHREADS + tid] = g_bn[i * NTHREADS + tid];
    if (tid < TILE_M) {
        // a = ||x||^2: sequential fp32 chain (must match reference grid)
        const float* x = lat + (size_t)(rowBase + tid) * DDIM;
        float s = 0.f;
        #pragma unroll
        for (int d = 0; d < DDIM; d++)
            s = __fadd_rn(s, __fmul_rn(__ldg(x + d), __ldg(x + d)));
        AsS[tid] = s;
        mkey[tid] = ~0ull;
    }

    // ---- A fragments: hi halves only (LDG + in-register convert) ----
    uint4 AH[KT];
    {
        const size_t r0 = (size_t)(rowBase + w * 16 + qid) * DDIM;
        const size_t r1 = r0 + 8 * DDIM;
        #pragma unroll
        for (int kt = 0; kt < KT; kt++) {
            const int k0 = kt * 16 + 2 * qsub;
            float2 x00 = __ldg((const float2*)(lat + r0 + k0));
            float2 x10 = __ldg((const float2*)(lat + r1 + k0));
            float2 x02 = __ldg((const float2*)(lat + r0 + k0 + 8));
            float2 x12 = __ldg((const float2*)(lat + r1 + k0 + 8));
            AH[kt] = make_uint4(
                pack_h2(__float2half_rn(x00.x), __float2half_rn(x00.y)),
                pack_h2(__float2half_rn(x10.x), __float2half_rn(x10.y)),
                pack_h2(__float2half_rn(x02.x), __float2half_rn(x02.y)),
                pack_h2(__float2half_rn(x12.x), __float2half_rn(x12.y)));
        }
    }

    // ---- pass 1: 4 MMAs per nt; dump S to smem as fp16 (stateless) ----
    {
        const int row0 = w * 16 + qid;          // j=0 row
        __half* hp0 = &hS[row0 * HSTRIDE + qsub * 2];
        __half* hp1 = &hS[(row0 + 8) * HSTRIDE + qsub * 2];
        #pragma unroll 4
        for (int nt = 0; nt < NT_TILES; nt++) {
            uint2 Bc[KT];
            #pragma unroll
            for (int kt = 0; kt < KT; kt++)
                Bc[kt] = __ldg(&g_epack[(kt * KEMB + nt * 8 + qid) * 4 + qsub]);

            float s[4] = {0.f, 0.f, 0.f, 0.f};
            #pragma unroll
            for (int kt = 0; kt < KT; kt++)
                mma_f16(s, AH[kt], Bc[kt].x, Bc[kt].y);

            *(__half2*)(hp0 + nt * 8) = __floats2half2_rn(s[0], s[1]);
            *(__half2*)(hp1 + nt * 8) = __floats2half2_rn(s[2], s[3]);
        }
    }
    __syncthreads();

    // ---- scan pass A: per half-row min of h = b - S/256 ----
    const int srow = tid >> 1;
    const int shalf = tid & 1;
    const __half* sp = &hS[srow * HSTRIDE + shalf * 256];
    const float* bp = &BnS[shalf * 256];
    float gmin = CUDART_INF_F;
    #pragma unroll 8
    for (int i = 0; i < 64; i++) {
        uint2 u = *(const uint2*)(sp + i * 4);
        float2 f0 = __half22float2(*(const __half2*)&u.x);
        float2 f1 = __half22float2(*(const __half2*)&u.y);
        float h0 = __fmaf_rn(f0.x, -INV256, bp[i * 4 + 0]);
        float h1 = __fmaf_rn(f0.y, -INV256, bp[i * 4 + 1]);
        float h2 = __fmaf_rn(f1.x, -INV256, bp[i * 4 + 2]);
        float h3 = __fmaf_rn(f1.y, -INV256, bp[i * 4 + 3]);
        gmin = fminf(gmin, fminf(fminf(h0, h1), fminf(h2, h3)));
    }
    gmin = fminf(gmin, __shfl_xor_sync(0xffffffffu, gmin, 1));
    const float thr = gmin + BAND;

    // ---- scan pass B: rescore every band col exactly ----
    {
        const float* xr = lat + (size_t)(rowBase + srow) * DDIM;
        const float aR = AsS[srow];
        #pragma unroll 4
        for (int i = 0; i < 64; i++) {
            uint2 u = *(const uint2*)(sp + i * 4);
            float2 f0 = __half22float2(*(const __half2*)&u.x);
            float2 f1 = __half22float2(*(const __half2*)&u.y);
            float h[4];
            h[0] = __fmaf_rn(f0.x, -INV256, bp[i * 4 + 0]);
            h[1] = __fmaf_rn(f0.y, -INV256, bp[i * 4 + 1]);
            h[2] = __fmaf_rn(f1.x, -INV256, bp[i * 4 + 2]);
            h[3] = __fmaf_rn(f1.y, -INV256, bp[i * 4 + 3]);
            #pragma unroll
            for (int q = 0; q < 4; q++) {
                if (h[q] <= thr) {
                    int col = shalf * 256 + i * 4 + q;
                    float d = exact_dist4(xr, emb + (size_t)col * DDIM, aR, BnS[col]);
                    atomicMin(&mkey[srow],
                        ((unsigned long long)__float_as_uint(d) << 32) | (unsigned)col);
                }
            }
        }
    }
    __syncthreads();
    if (tid < TILE_M) IdxS[tid] = (int)(mkey[tid] & 0xFFFFFFFFull);
    __syncthreads();

    // ---- gather + straight-through write (scalar stores) + fp64 loss ----
    double ls = 0.0;
    {
        const int seg  = tid & 15;
        const int rsub = tid >> 4;
        #pragma unroll
        for (int p = 0; p < 8; p++) {
            int row = p * 8 + rsub;
            int idx = IdxS[row];
            float4 q = __ldg((const float4*)(emb + (size_t)idx * DDIM + seg * 4));
            float4 l = __ldg((const float4*)(lat + (size_t)(rowBase + row) * DDIM + seg * 4));
            float t0 = q.x - l.x, t1 = q.y - l.y, t2 = q.z - l.z, t3 = q.w - l.w;
            ls += (double)t0 * t0 + (double)t1 * t1
                + (double)t2 * t2 + (double)t3 * t3;
            float* o = quant + (size_t)(rowBase + row) * DDIM + seg * 4;
            o[0] = l.x + t0;
            o[1] = l.y + t1;
            o[2] = l.z + t2;
            o[3] = l.w + t3;
        }
    }

    #pragma unroll
    for (int off = 16; off >= 1; off >>= 1)
        ls += __shfl_xor_sync(0xffffffffu, ls, off);
    if (lane == 0) Wsum[w] = ls;
    __syncthreads();

    // ---- publish partial, then last CTA reduces (deterministic order) ----
    if (tid == 0) {
        g_part[blockIdx.x] = Wsum[0] + Wsum[1] + Wsum[2] + Wsum[3];
        __threadfence();
        int ticket = atomicAdd(&g_cnt, 1);
        lastFlag = (ticket == NCTAS - 1) ? 1 : 0;
    }
    __syncthreads();
    if (lastFlag) {
        double s = 0.0;
        #pragma unroll
        for (int i = 0; i < NCTAS / NTHREADS; i++)     // fixed order: 8 per thread
            s += g_part[i * NTHREADS + tid];
        #pragma unroll
        for (int off = 16; off >= 1; off >>= 1)
            s += __shfl_xor_sync(0xffffffffu, s, off);
        if (lane == 0) Wsum[w] = s;
        __syncthreads();
        if (tid == 0) {
            double m = (Wsum[0] + Wsum[1] + Wsum[2] + Wsum[3])
                       / (double)((size_t)NROWS * DDIM);
            out[0] = (float)(1.25 * m);
            g_cnt = 0;   // self-reset for graph replay
        }
    }
}

extern "C" void kernel_launch(void* const* d_in, const int* in_sizes, int n_in,
                              void* d_out, int out_size) {
    const float* lat = (const float*)d_in[0];   // latents  [65536, 64]
    const float* emb = (const float*)d_in[1];   // embedding [512, 64]
    float* out = (float*)d_out;

    const size_t dynsmem = (size_t)TILE_M * HSTRIDE * sizeof(__half);  // 67,072 B
    cudaFuncSetAttribute(vq_mma_kernel,
                         cudaFuncAttributeMaxDynamicSharedMemorySize, (int)dynsmem);
    vq_epack_kernel<<<8, 128>>>(emb);
    vq_mma_kernel<<<NCTAS, NTHREADS, dynsmem>>>(lat, emb, out);
}

// round 16
// speedup vs baseline: 2.4764x; 2.4764x over previous
#include <cuda_runtime.h>
#include <cuda_fp16.h>
#include <math_constants.h>
#include <cstdint>

// VectorQuantizer: two-phase fp16 hi*hi mma.sync filter + exact fp32 rescore.
// latents [65536,64] f32, embedding [512,64] f32.
// out[0] = vq_loss, out[1..] = quantized_st (4B-aligned -> scalar stores).
//
// Phase 1: 4 MMAs/nt, running fminf of h = b - S/256 (no state but 2 floats).
// Phase 2: re-run the same 4 MMAs/nt with thr = gmin + BAND known; h <= thr
// (filter error <= 4.8e-4, BAND = 1.5e-3, 3x margin) -> exact rescore with the
// R13-validated ascending fmaf chain, fl(fl(a+b)-2c), packed-key atomicMin
// (first-index ties). Unconditionally sound: phase 2 revisits all 512 cols.
// 8 MMAs/nt vs exact 3-pass's 12; epilogue is stateless per nt (R13/14/15
// lesson: ANY per-nt candidate bookkeeping costs more than the MMAs saved).

#define NROWS 65536
#define KEMB 512
#define DDIM 64
#define TILE_M 64
#define NCTAS (NROWS / TILE_M)   // 1024
#define NTHREADS 128             // 4 warps; warp owns 16 rows (1 m16 tile)
#define NT_TILES (KEMB / 8)      // 64
#define KT 4                     // K = 64 = 4 x k16
#define BAND 1.5e-3f
#define INV256 0.00390625f

__device__ uint2  g_epack[KT * KEMB * 4];  // 64 KB: B cells (hi only)
__device__ float  g_bn[KEMB];              // ||e||^2 exact chains
__device__ double g_part[NCTAS];
__device__ int    g_cnt = 0;               // last-CTA ticket (self-resetting)

__device__ __forceinline__ uint32_t pack_h2(__half lo, __half hi) {
    return (uint32_t)__half_as_ushort(lo) | ((uint32_t)__half_as_ushort(hi) << 16);
}
__device__ __forceinline__ void mma_f16(float* d, const uint4 a,
                                        uint32_t b0, uint32_t b1) {
    asm volatile(
        "mma.sync.aligned.m16n8k16.row.col.f32.f16.f16.f32 "
        "{%0,%1,%2,%3}, {%4,%5,%6,%7}, {%8,%9}, {%0,%1,%2,%3};"
        : "+f"(d[0]), "+f"(d[1]), "+f"(d[2]), "+f"(d[3])
        : "r"(a.x), "r"(a.y), "r"(a.z), "r"(a.w), "r"(b0), "r"(b1));
}
// exact R1-class distance: ascending-d fmaf chain + fl(fl(a+b) - 2c)
__device__ __forceinline__ float exact_dist4(const float* __restrict__ x,
                                             const float* __restrict__ e,
                                             float a, float b) {
    float c = 0.f;
    #pragma unroll
    for (int d = 0; d < DDIM; d += 4) {
        float4 xv = __ldg((const float4*)(x + d));
        float4 ev = __ldg((const float4*)(e + d));
        c = __fmaf_rn(xv.x, ev.x, c);
        c = __fmaf_rn(xv.y, ev.y, c);
        c = __fmaf_rn(xv.z, ev.z, c);
        c = __fmaf_rn(xv.w, ev.w, c);
    }
    return __fsub_rn(__fadd_rn(a, b), 2.0f * c);
}

// ---------------- pre-kernel (8 blocks): E hi-cells + ||e||^2 ----------------
__global__ __launch_bounds__(128)
void vq_epack_kernel(const float* __restrict__ emb) {
    const int tid = threadIdx.x;
    const int b = blockIdx.x;
    if (tid < 64) {                 // Bn: sequential fp32 chain on raw e
        int n = b * 64 + tid;
        const float* e = emb + (size_t)n * DDIM;
        float s = 0.f;
        #pragma unroll
        for (int d = 0; d < DDIM; d++)
            s = __fadd_rn(s, __fmul_rn(e[d], e[d]));
        g_bn[n] = s;
    }
    #pragma unroll
    for (int s = 0; s < 8; s++) {
        int ci = s * 128 + tid;
        int kt = ci >> 8, rem = ci & 255;
        int nl = rem >> 2, qs = rem & 3;
        int n = b * 64 + nl;
        int k0 = kt * 16 + 2 * qs;
        float2 e01 = __ldg((const float2*)(emb + (size_t)n * DDIM + k0));
        float2 e89 = __ldg((const float2*)(emb + (size_t)n * DDIM + k0 + 8));
        __half h0 = __float2half_rn(512.f * e01.x);
        __half h1 = __float2half_rn(512.f * e01.y);
        __half h2 = __float2half_rn(512.f * e89.x);
        __half h3 = __float2half_rn(512.f * e89.y);
        g_epack[(kt * KEMB + n) * 4 + qs] = make_uint2(pack_h2(h0, h1), pack_h2(h2, h3));
    }
}

// ---------------- main kernel ----------------
__global__ __launch_bounds__(NTHREADS, 4)
void vq_mma_kernel(const float* __restrict__ lat,
                   const float* __restrict__ emb,
                   float* __restrict__ out /* d_out; quant = out+1 */)
{
    __shared__ float    BnS[KEMB];
    __shared__ float    AsS[TILE_M];
    __shared__ unsigned long long mkey[TILE_M];
    __shared__ int      IdxS[TILE_M];
    __shared__ double   Wsum[4];
    __shared__ int      lastFlag;

    float* quant = out + 1;

    const int tid  = threadIdx.x;
    const int w    = tid >> 5;
    const int lane = tid & 31;
    const int qid  = lane >> 2;
    const int qsub = lane & 3;
    const int rowBase = blockIdx.x * TILE_M;

    #pragma unroll
    for (int i = 0; i < 4; i++) BnS[i * NTHREADS + tid] = g_bn[i * NTHREADS + tid];
    if (tid < TILE_M) {
        // a = ||x||^2: sequential fp32 chain (must match reference grid)
        const float* x = lat + (size_t)(rowBase + tid) * DDIM;
        float s = 0.f;
        #pragma unroll
        for (int d = 0; d < DDIM; d++)
            s = __fadd_rn(s, __fmul_rn(__ldg(x + d), __ldg(x + d)));
        AsS[tid] = s;
        mkey[tid] = ~0ull;
    }

    // ---- A fragments: hi halves only (LDG + in-register convert) ----
    uint4 AH[KT];
    {
        const size_t r0 = (size_t)(rowBase + w * 16 + qid) * DDIM;
        const size_t r1 = r0 + 8 * DDIM;
        #pragma unroll
        for (int kt = 0; kt < KT; kt++) {
            const int k0 = kt * 16 + 2 * qsub;
            float2 x00 = __ldg((const float2*)(lat + r0 + k0));
            float2 x10 = __ldg((const float2*)(lat + r1 + k0));
            float2 x02 = __ldg((const float2*)(lat + r0 + k0 + 8));
            float2 x12 = __ldg((const float2*)(lat + r1 + k0 + 8));
            AH[kt] = make_uint4(
                pack_h2(__float2half_rn(x00.x), __float2half_rn(x00.y)),
                pack_h2(__float2half_rn(x10.x), __float2half_rn(x10.y)),
                pack_h2(__float2half_rn(x02.x), __float2half_rn(x02.y)),
                pack_h2(__float2half_rn(x12.x), __float2half_rn(x12.y)));
        }
    }
    __syncthreads();

    // ---- phase 1: 4 MMAs/nt, running min of h (stateless but rmin) ----
    float rmin0 = CUDART_INF_F, rmin1 = CUDART_INF_F;
    #pragma unroll 2
    for (int nt = 0; nt < NT_TILES; nt++) {
        uint2 Bc[KT];
        #pragma unroll
        for (int kt = 0; kt < KT; kt++)
            Bc[kt] = __ldg(&g_epack[(kt * KEMB + nt * 8 + qid) * 4 + qsub]);

        float s[4] = {0.f, 0.f, 0.f, 0.f};
        #pragma unroll
        for (int kt = 0; kt < KT; kt++)
            mma_f16(s, AH[kt], Bc[kt].x, Bc[kt].y);

        const int col0 = nt * 8 + qsub * 2;
        const float b0 = BnS[col0], b1 = BnS[col0 + 1];
        rmin0 = fminf(rmin0, fminf(__fmaf_rn(s[0], -INV256, b0),
                                   __fmaf_rn(s[1], -INV256, b1)));
        rmin1 = fminf(rmin1, fminf(__fmaf_rn(s[2], -INV256, b0),
                                   __fmaf_rn(s[3], -INV256, b1)));
    }
    // quad reduce -> per-row gmin, threshold
    rmin0 = fminf(rmin0, __shfl_xor_sync(0xffffffffu, rmin0, 1));
    rmin0 = fminf(rmin0, __shfl_xor_sync(0xffffffffu, rmin0, 2));
    rmin1 = fminf(rmin1, __shfl_xor_sync(0xffffffffu, rmin1, 1));
    rmin1 = fminf(rmin1, __shfl_xor_sync(0xffffffffu, rmin1, 2));
    const float thr0 = rmin0 + BAND;
    const float thr1 = rmin1 + BAND;

    // ---- phase 2: re-run MMAs; rescore any h <= thr exactly ----
    {
        const int rowL0 = w * 16 + qid;
        const int rowL1 = rowL0 + 8;
        const float* xr0 = lat + (size_t)(rowBase + rowL0) * DDIM;
        const float* xr1 = lat + (size_t)(rowBase + rowL1) * DDIM;
        const float a0 = AsS[rowL0];
        const float a1 = AsS[rowL1];
        #pragma unroll 2
        for (int nt = 0; nt < NT_TILES; nt++) {
            uint2 Bc[KT];
            #pragma unroll
            for (int kt = 0; kt < KT; kt++)
                Bc[kt] = __ldg(&g_epack[(kt * KEMB + nt * 8 + qid) * 4 + qsub]);

            float s[4] = {0.f, 0.f, 0.f, 0.f};
            #pragma unroll
            for (int kt = 0; kt < KT; kt++)
                mma_f16(s, AH[kt], Bc[kt].x, Bc[kt].y);

            const int col0 = nt * 8 + qsub * 2;
            const float b0 = BnS[col0], b1 = BnS[col0 + 1];
            float h00 = __fmaf_rn(s[0], -INV256, b0);
            float h01 = __fmaf_rn(s[1], -INV256, b1);
            float h10 = __fmaf_rn(s[2], -INV256, b0);
            float h11 = __fmaf_rn(s[3], -INV256, b1);
            if (h00 <= thr0) {
                float d = exact_dist4(xr0, emb + (size_t)col0 * DDIM, a0, b0);
                atomicMin(&mkey[rowL0],
                    ((unsigned long long)__float_as_uint(d) << 32) | (unsigned)col0);
            }
            if (h01 <= thr0) {
                float d = exact_dist4(xr0, emb + (size_t)(col0 + 1) * DDIM, a0, b1);
                atomicMin(&mkey[rowL0],
                    ((unsigned long long)__float_as_uint(d) << 32) | (unsigned)(col0 + 1));
            }
            if (h10 <= thr1) {
                float d = exact_dist4(xr1, emb + (size_t)col0 * DDIM, a1, b0);
                atomicMin(&mkey[rowL1],
                    ((unsigned long long)__float_as_uint(d) << 32) | (unsigned)col0);
            }
            if (h11 <= thr1) {
                float d = exact_dist4(xr1, emb + (size_t)(col0 + 1) * DDIM, a1, b1);
                atomicMin(&mkey[rowL1],
                    ((unsigned long long)__float_as_uint(d) << 32) | (unsigned)(col0 + 1));
            }
        }
    }
    __syncthreads();
    if (tid < TILE_M) IdxS[tid] = (int)(mkey[tid] & 0xFFFFFFFFull);
    __syncthreads();

    // ---- gather + straight-through write (scalar stores) + fp64 loss ----
    double ls = 0.0;
    {
        const int seg  = tid & 15;
        const int rsub = tid >> 4;
        #pragma unroll
        for (int p = 0; p < 8; p++) {
            int row = p * 8 + rsub;
            int idx = IdxS[row];
            float4 q = __ldg((const float4*)(emb + (size_t)idx * DDIM + seg * 4));
            float4 l = __ldg((const float4*)(lat + (size_t)(rowBase + row) * DDIM + seg * 4));
            float t0 = q.x - l.x, t1 = q.y - l.y, t2 = q.z - l.z, t3 = q.w - l.w;
            ls += (double)t0 * t0 + (double)t1 * t1
                + (double)t2 * t2 + (double)t3 * t3;
            float* o = quant + (size_t)(rowBase + row) * DDIM + seg * 4;
            o[0] = l.x + t0;
            o[1] = l.y + t1;
            o[2] = l.z + t2;
            o[3] = l.w + t3;
        }
    }

    #pragma unroll
    for (int off = 16; off >= 1; off >>= 1)
        ls += __shfl_xor_sync(0xffffffffu, ls, off);
    if (lane == 0) Wsum[w] = ls;
    __syncthreads();

    // ---- publish partial, then last CTA reduces (deterministic order) ----
    if (tid == 0) {
        g_part[blockIdx.x] = Wsum[0] + Wsum[1] + Wsum[2] + Wsum[3];
        __threadfence();
        int ticket = atomicAdd(&g_cnt, 1);
        lastFlag = (ticket == NCTAS - 1) ? 1 : 0;
    }
    __syncthreads();
    if (lastFlag) {
        double s = 0.0;
        #pragma unroll
        for (int i = 0; i < NCTAS / NTHREADS; i++)     // fixed order: 8 per thread
            s += g_part[i * NTHREADS + tid];
        #pragma unroll
        for (int off = 16; off >= 1; off >>= 1)
            s += __shfl_xor_sync(0xffffffffu, s, off);
        if (lane == 0) Wsum[w] = s;
        __syncthreads();
        if (tid == 0) {
            double m = (Wsum[0] + Wsum[1] + Wsum[2] + Wsum[3])
                       / (double)((size_t)NROWS * DDIM);
            out[0] = (float)(1.25 * m);
            g_cnt = 0;   // self-reset for graph replay
        }
    }
}

extern "C" void kernel_launch(void* const* d_in, const int* in_sizes, int n_in,
                              void* d_out, int out_size) {
    const float* lat = (const float*)d_in[0];   // latents  [65536, 64]
    const float* emb = (const float*)d_in[1];   // embedding [512, 64]
    float* out = (float*)d_out;

    vq_epack_kernel<<<8, 128>>>(emb);
    vq_mma_kernel<<<NCTAS, NTHREADS>>>(lat, emb, out);
}